// round 7
// baseline (speedup 1.0000x reference)
#include <cuda_runtime.h>

// Problem shape (fixed by reference setup_inputs)
#define NBATCH 2
#define DD 160
#define HH 192
#define WW 224
#define HHWW (HH * WW)

// Tiling: thread = 4 consecutive x-pixels (float4), block tile 32x16, rolling z.
#define TX 32
#define TY 16
#define TZ 16
#define NTX 8                    // blockDim.x (8 * 4 = 32 x-pixels)
#define NTHREADS 128
#define HROWS (TY + 2)           // 18
#define VROW 10                  // float4 per smem row: [x0-4, x0+36)
#define SROW (VROW * 4)          // 40 floats
#define VEC_ELEMS (HROWS * VROW) // 180
#define GXB (WW / TX)            // 7
#define GYB (HH / TY)            // 12
#define GZB (NBATCH * (DD / TZ)) // 20
#define TOTAL_BLOCKS (GXB * GYB * GZB)  // 1680

__device__ double g_partial[TOTAL_BLOCKS];
__device__ unsigned int g_count = 0;   // self-wrapping via atomicInc

__global__ void __launch_bounds__(NTHREADS, 7) grad_loss_kernel(
    const float* __restrict__ x, const float* __restrict__ y,
    float* __restrict__ out)
{
    __shared__ float sd[2][HROWS][SROW];   // double-buffered (x-y) diff plane

    const int txq = threadIdx.x;           // 0..7
    const int ty  = threadIdx.y;           // 0..15
    const int tid = ty * NTX + txq;

    const int x0 = blockIdx.x * TX;
    const int y0 = blockIdx.y * TY;
    const int bz = blockIdx.z;
    const int n  = bz / (DD / TZ);
    const int z0 = (bz % (DD / TZ)) * TZ;
    const int bid = blockIdx.x + GXB * (blockIdx.y + GYB * blockIdx.z);

    const float* xb = x + (size_t)n * DD * HHWW;
    const float* yb = y + (size_t)n * DD * HHWW;

    // ---- plane-invariant halo-load bookkeeping (2 predicated float4 slots) ----
    // x-halo is exactly one float4 per side, so each float4 is all-or-nothing valid.
    int  goff[2], soff[2];
    bool ok2[2];
#pragma unroll
    for (int i = 0; i < 2; ++i) {
        const int idx = tid + i * NTHREADS;
        const int r   = idx / VROW;
        const int c   = idx - r * VROW;
        const int gy  = y0 - 1 + r;
        const int gxb = x0 - 4 + 4 * c;
        const bool v  = (idx < VEC_ELEMS) &&
                        (gy >= 0) && (gy < HH) && (gxb >= 0) && (gxb + 3 < WW);
        ok2[i]  = v;
        goff[i] = v ? (gy * WW + gxb) : 0;
        soff[i] = r * SROW + 4 * c;
    }
    const bool act1 = (tid + NTHREADS < VEC_ELEMS);

    // Rolling z-state per output column (4 cols): A=sx*sy, B=dx*sy, C=sx*dy
    float A2[4], A1[4], B2[4], B1[4], C2[4], C1[4];
#pragma unroll
    for (int c = 0; c < 4; ++c)
        A2[c] = A1[c] = B2[c] = B1[c] = C2[c] = C1[c] = 0.f;
    float acc = 0.f;

    // ---- prologue: load plane gz = z0-1 into buffer 0 ----
    {
        const int gz = z0 - 1;
        const bool zok = (gz >= 0);
        const float* xp = xb + (size_t)(zok ? gz : 0) * HHWW;
        const float* yp = yb + (size_t)(zok ? gz : 0) * HHWW;
#pragma unroll
        for (int i = 0; i < 2; ++i) {
            const bool o = zok && ok2[i];
            float4 d = make_float4(0.f, 0.f, 0.f, 0.f);
            if (o) {
                const float4 a = __ldg((const float4*)(xp + goff[i]));
                const float4 b = __ldg((const float4*)(yp + goff[i]));
                d = make_float4(a.x - b.x, a.y - b.y, a.z - b.z, a.w - b.w);
            }
            if (i == 0 || act1)
                *(float4*)(&sd[0][0][0] + soff[i]) = d;
        }
    }
    __syncthreads();

    const int lc = 4 + 4 * txq;   // smem col of this thread's first output pixel

    for (int p = 0; p < TZ + 2; ++p) {
        // ---- (a) issue prefetch LDGs for plane gz = z0 + p ----
        float4 v0 = make_float4(0.f, 0.f, 0.f, 0.f);
        float4 v1 = make_float4(0.f, 0.f, 0.f, 0.f);
        const bool haveNext = (p <= TZ);
        if (haveNext) {
            const int gz = z0 + p;
            const bool zok = (gz < DD);
            const float* xp = xb + (size_t)(zok ? gz : 0) * HHWW;
            const float* yp = yb + (size_t)(zok ? gz : 0) * HHWW;
            if (zok && ok2[0]) {
                const float4 a = __ldg((const float4*)(xp + goff[0]));
                const float4 b = __ldg((const float4*)(yp + goff[0]));
                v0 = make_float4(a.x - b.x, a.y - b.y, a.z - b.z, a.w - b.w);
            }
            if (zok && ok2[1]) {
                const float4 a = __ldg((const float4*)(xp + goff[1]));
                const float4 b = __ldg((const float4*)(yp + goff[1]));
                v1 = make_float4(a.x - b.x, a.y - b.y, a.z - b.z, a.w - b.w);
            }
        }

        // ---- (b) compute plane p from buffer p&1 (overlaps prefetch) ----
        // Incremental accumulation over the 3 y-rows; x-neighbors via shuffle.
        const int bsel = p & 1;
        float A[4], B[4], C[4];
#pragma unroll
        for (int k = 0; k < 3; ++k) {
            const float* row = &sd[bsel][ty + k][0];
            const float4 d = *(const float4*)(row + lc);
            float dl = __shfl_up_sync(0xffffffffu, d.w, 1);
            float dr = __shfl_down_sync(0xffffffffu, d.x, 1);
            if (txq == 0)       dl = row[lc - 1];   // col 3
            if (txq == NTX - 1) dr = row[lc + 4];   // col 36

            float rsx[4], rdx[4];
            rsx[0] = fmaf(2.f, d.x, dl + d.y);
            rsx[1] = fmaf(2.f, d.y, d.x + d.z);
            rsx[2] = fmaf(2.f, d.z, d.y + d.w);
            rsx[3] = fmaf(2.f, d.w, d.z + dr);
            rdx[0] = dl - d.y;
            rdx[1] = d.x - d.z;
            rdx[2] = d.y - d.w;
            rdx[3] = d.z - dr;

#pragma unroll
            for (int c = 0; c < 4; ++c) {
                if (k == 0) {
                    A[c] = rsx[c];
                    C[c] = rsx[c];
                    B[c] = rdx[c];
                } else if (k == 1) {
                    A[c] = fmaf(2.f, rsx[c], A[c]);
                    B[c] = fmaf(2.f, rdx[c], B[c]);
                } else {
                    A[c] += rsx[c];
                    C[c] -= rsx[c];
                    B[c] += rdx[c];
                }
            }
        }

#pragma unroll
        for (int c = 0; c < 4; ++c) {
            if (p >= 2) {   // emit output for plane z0 + p - 2
                const float fx = A2[c] - A[c];                     // diff_z(A)
                const float fy = fmaf(2.f, C1[c], C2[c] + C[c]);   // smooth_z(C)
                const float fz = fmaf(2.f, B1[c], B2[c] + B[c]);   // smooth_z(B)
                acc = fmaf(fx, fx, acc);
                acc = fmaf(fy, fy, acc);
                acc = fmaf(fz, fz, acc);
            }
            A2[c] = A1[c]; A1[c] = A[c];
            B2[c] = B1[c]; B1[c] = B[c];
            C2[c] = C1[c]; C1[c] = C[c];
        }

        // ---- (c) store prefetched plane into other buffer ----
        if (haveNext) {
            float* sn = &sd[bsel ^ 1][0][0];
            *(float4*)(sn + soff[0]) = v0;
            if (act1) *(float4*)(sn + soff[1]) = v1;
        }
        __syncthreads();
    }

    // ---- block reduction (deterministic order) ----
#pragma unroll
    for (int o = 16; o; o >>= 1)
        acc += __shfl_down_sync(0xffffffffu, acc, o);

    __shared__ float warpsum[4];
    __shared__ bool  s_last;
    const int wid  = tid >> 5;
    const int lane = tid & 31;
    if (lane == 0) warpsum[wid] = acc;
    __syncthreads();
    if (tid == 0) {
        float s = 0.f;
#pragma unroll
        for (int w = 0; w < 4; ++w) s += warpsum[w];
        g_partial[bid] = (double)s;
        __threadfence();
        const unsigned old = atomicInc(&g_count, TOTAL_BLOCKS - 1); // wraps to 0
        s_last = (old == TOTAL_BLOCKS - 1);
    }
    __syncthreads();

    // ---- last block: sum partials, write scalar output ----
    if (s_last) {
        double ds = 0.0;
        for (int i = tid; i < TOTAL_BLOCKS; i += NTHREADS)
            ds += g_partial[i];
#pragma unroll
        for (int o = 16; o; o >>= 1)
            ds += __shfl_down_sync(0xffffffffu, ds, o);
        __shared__ double dwarp[4];
        if (lane == 0) dwarp[wid] = ds;
        __syncthreads();
        if (tid == 0) {
            double t = 0.0;
#pragma unroll
            for (int w = 0; w < 4; ++w) t += dwarp[w];
            out[0] = (float)(t / ((double)NBATCH * DD * HH * WW));
        }
    }
}

extern "C" void kernel_launch(void* const* d_in, const int* in_sizes, int n_in,
                              void* d_out, int out_size)
{
    const float* x = (const float*)d_in[0];
    const float* y = (const float*)d_in[1];
    float* out = (float*)d_out;

    dim3 block(NTX, TY, 1);          // 8 x 16 = 128 threads
    dim3 grid(GXB, GYB, GZB);        // 7 x 12 x 20 = 1680
    grad_loss_kernel<<<grid, block>>>(x, y, out);
}

// round 8
// speedup vs baseline: 1.1492x; 1.1492x over previous
#include <cuda_runtime.h>

// Problem shape (fixed by reference setup_inputs)
#define NBATCH 2
#define DD 160
#define HH 192
#define WW 224

// Tiling — exactly the round-2 configuration (best measured main kernel)
#define TX 32          // x tile (== blockDim.x)
#define TY 16          // y tile
#define TZ 32          // z chunk per block
#define YPT 2          // y outputs per thread (blockDim.y = 8)
#define NTHREADS 256
#define HROWS (TY + 2)              // 18
#define HCOLS (TX + 2)              // 34
#define HALO_ELEMS (HROWS * HCOLS)  // 612
#define GXB 7
#define GYB 12
#define GZB (NBATCH * (DD / TZ))            // 10
#define TOTAL_BLOCKS (GXB * GYB * GZB)      // 840

__device__ double g_partial[TOTAL_BLOCKS];
__device__ unsigned int g_count = 0;   // self-wrapping via atomicInc

__global__ void __launch_bounds__(NTHREADS) grad_loss_kernel(
    const float* __restrict__ x, const float* __restrict__ y,
    float* __restrict__ out)
{
    __shared__ float sd[2][HROWS][HCOLS];   // double-buffered (x-y) plane

    const int tx  = threadIdx.x;
    const int ty  = threadIdx.y;
    const int tid = ty * 32 + tx;

    const int x0 = blockIdx.x * TX;
    const int y0 = blockIdx.y * TY;
    const int bz = blockIdx.z;
    const int n  = bz / (DD / TZ);
    const int z0 = (bz % (DD / TZ)) * TZ;
    const int bid = blockIdx.x + GXB * (blockIdx.y + GYB * blockIdx.z);

    const float* xb = x + (size_t)n * DD * HH * WW;
    const float* yb = y + (size_t)n * DD * HH * WW;

    // ---- plane-invariant halo-load bookkeeping (computed ONCE) ----
    int  off[3];
    int  sidx[3];
    bool ok[3];
#pragma unroll
    for (int i = 0; i < 3; ++i) {
        const int idx = tid + i * NTHREADS;
        const int r   = idx / HCOLS;
        const int c   = idx - r * HCOLS;
        const int gy  = y0 - 1 + r;
        const int gx  = x0 - 1 + c;
        const bool v  = (idx < HALO_ELEMS) &&
                        (gy >= 0) && (gy < HH) && (gx >= 0) && (gx < WW);
        ok[i]   = v;
        off[i]  = v ? (gy * WW + gx) : 0;
        sidx[i] = idx;
    }

    // Rolling per-plane partials: A = sx*sy, B = dx*sy, C = sx*dy
    float A1[YPT], A2[YPT], B1[YPT], B2[YPT], C1[YPT], C2[YPT];
#pragma unroll
    for (int j = 0; j < YPT; ++j)
        A1[j] = A2[j] = B1[j] = B2[j] = C1[j] = C2[j] = 0.f;
    float acc = 0.f;

    // ---- prologue: load plane gz = z0-1 into buffer 0 ----
    {
        const int gz = z0 - 1;
        const bool zok = (gz >= 0);   // z0-1 < DD always
        const float* xp = xb + (size_t)gz * HH * WW;
        const float* yp = yb + (size_t)gz * HH * WW;
        float v[3];
#pragma unroll
        for (int i = 0; i < 3; ++i)
            v[i] = (zok && ok[i]) ? (__ldg(xp + off[i]) - __ldg(yp + off[i])) : 0.f;
#pragma unroll
        for (int i = 0; i < 3; ++i)
            if (i < 2 || sidx[i] < HALO_ELEMS)
                (&sd[0][0][0])[sidx[i]] = v[i];
    }
    __syncthreads();

    const int lx = tx + 1;

    for (int p = 0; p < TZ + 2; ++p) {
        // ---- issue prefetch LDGs for plane p+1 (gz = z0 + p) ----
        float vn[3];
        const bool last = (p == TZ + 1);
        if (!last) {
            const int gz = z0 + p;
            const bool zok = (gz < DD);   // gz >= 0 always here
            const float* xp = xb + (size_t)gz * HH * WW;
            const float* yp = yb + (size_t)gz * HH * WW;
#pragma unroll
            for (int i = 0; i < 3; ++i)
                vn[i] = (zok && ok[i]) ? (__ldg(xp + off[i]) - __ldg(yp + off[i])) : 0.f;
        }

        // ---- compute plane p from buffer p&1 (overlaps the LDGs above) ----
        const int b = p & 1;
        float rsx[YPT + 2], rdx[YPT + 2];
#pragma unroll
        for (int k = 0; k < YPT + 2; ++k) {
            const int s = ty * YPT + k;
            const float dm = sd[b][s][lx - 1];
            const float d0 = sd[b][s][lx];
            const float dp = sd[b][s][lx + 1];
            rsx[k] = fmaf(2.f, d0, dm + dp);
            rdx[k] = dm - dp;
        }
#pragma unroll
        for (int j = 0; j < YPT; ++j) {
            const float A = fmaf(2.f, rsx[j + 1], rsx[j] + rsx[j + 2]);
            const float C = rsx[j] - rsx[j + 2];
            const float B = fmaf(2.f, rdx[j + 1], rdx[j] + rdx[j + 2]);

            if (p >= 2) {   // emit output for plane z0 + p - 2
                const float fx = A2[j] - A;                     // diff_z(A)
                const float fy = fmaf(2.f, C1[j], C2[j] + C);   // smooth_z(C)
                const float fz = fmaf(2.f, B1[j], B2[j] + B);   // smooth_z(B)
                acc = fmaf(fx, fx, acc);
                acc = fmaf(fy, fy, acc);
                acc = fmaf(fz, fz, acc);
            }
            A2[j] = A1[j]; A1[j] = A;
            B2[j] = B1[j]; B1[j] = B;
            C2[j] = C1[j]; C1[j] = C;
        }

        // ---- store prefetched plane into the other buffer ----
        if (!last) {
            const int nb = b ^ 1;
#pragma unroll
            for (int i = 0; i < 3; ++i)
                if (i < 2 || sidx[i] < HALO_ELEMS)
                    (&sd[nb][0][0])[sidx[i]] = vn[i];
        }
        __syncthreads();
    }

    // ---- block reduction (deterministic order) ----
#pragma unroll
    for (int o = 16; o; o >>= 1)
        acc += __shfl_down_sync(0xffffffffu, acc, o);

    __shared__ float warpsum[8];
    __shared__ bool  s_last;
    if (tx == 0) warpsum[ty] = acc;
    __syncthreads();
    if (tid == 0) {
        float s = 0.f;
#pragma unroll
        for (int w = 0; w < 8; ++w) s += warpsum[w];
        g_partial[bid] = (double)s;
        __threadfence();
        const unsigned old = atomicInc(&g_count, TOTAL_BLOCKS - 1); // wraps to 0
        s_last = (old == TOTAL_BLOCKS - 1);
    }
    __syncthreads();

    // ---- last block: sum partials, write scalar output ----
    if (s_last) {
        double ds = 0.0;
        for (int i = tid; i < TOTAL_BLOCKS; i += NTHREADS)
            ds += g_partial[i];
#pragma unroll
        for (int o = 16; o; o >>= 1)
            ds += __shfl_down_sync(0xffffffffu, ds, o);
        __shared__ double dwarp[8];
        if (tx == 0) dwarp[ty] = ds;
        __syncthreads();
        if (tid == 0) {
            double t = 0.0;
#pragma unroll
            for (int w = 0; w < 8; ++w) t += dwarp[w];
            out[0] = (float)(t / ((double)NBATCH * DD * HH * WW));
        }
    }
}

extern "C" void kernel_launch(void* const* d_in, const int* in_sizes, int n_in,
                              void* d_out, int out_size)
{
    const float* x = (const float*)d_in[0];
    const float* y = (const float*)d_in[1];
    float* out = (float*)d_out;

    dim3 block(32, TY / YPT, 1);     // 256 threads
    dim3 grid(GXB, GYB, GZB);        // 7 x 12 x 10 = 840
    grad_loss_kernel<<<grid, block>>>(x, y, out);
}